// round 12
// baseline (speedup 1.0000x reference)
#include <cuda_runtime.h>
#include <float.h>

// Problem constants
#define HH 512
#define WW 512
#define MBS 8          // macroblock size
#define PR 8           // search range
#define NBR 64
#define NBC 64
#define NPAIR 14       // frame pairs actually used (motion[:-1])
#define NBATCH 4
#define CROPX 17
#define OUTD 478       // 512 - 2*17
#define LARGEC 65537.0f
#define MAX_STEPS 16
#define SW 84          // padded smem window stride (cols)

typedef unsigned long long ull;

// Motion vectors scratch: (dy, dx) per block. Static device global (no allocs).
__device__ int2 g_motion[NBATCH * NPAIR * NBR * NBC];

// LDSP points as (dx, dy) matching reference ordering; cost uses (y+dy, x+dx).
__constant__ int c_ldsp_dx[9] = { 0, -1, 1, -2, 0, 2, -1, 1, 0 };
__constant__ int c_ldsp_dy[9] = { -2, -1, -1, 0, 0, 0, 1, 1, 2 };
__constant__ int c_sdsp_dx[5] = { 0, -1, 0, 1, 0 };
__constant__ int c_sdsp_dy[5] = { -1, 0, 0, 0, 1 };

// Packed fp32x2 add (sm_103a): rounding identical to scalar FADD per lane.
__device__ __forceinline__ ull addp(ull a, ull b) {
    ull d;
    asm("add.rn.f32x2 %0, %1, %2;" : "=l"(d) : "l"(a), "l"(b));
    return d;
}
// Packed abs: clear both sign bits (bit-exact |x|); lands on the ALU pipe.
__device__ __forceinline__ ull absp(ull a) {
    ull d;
    asm("and.b64 %0, %1, 0x7FFFFFFF7FFFFFFF;" : "=l"(d) : "l"(a));
    return d;
}

// First-index argmin over a 16-lane group in 3 dependent steps.
// All values are >= 0 floats, so u32 order on the bit patterns == float order.
// Idle lanes must pass FLT_MAX. Returns the LOWEST lane holding the min
// (== jnp.argmin first-index, since lane-in-group is the candidate index).
__device__ __forceinline__ int argmin16(float v, unsigned gmask, int base) {
    unsigned bits = __float_as_uint(v);
    unsigned mn;
    asm("redux.sync.min.u32 %0, %1, %2;" : "=r"(mn) : "r"(bits), "r"(gmask));
    unsigned bal = __ballot_sync(gmask, bits == mn);
    return __ffs(bal >> base) - 1;
}

// One CTA: 8 macroblocks of one block-row segment. 128 threads = 8 groups of 16.
// Per group: lanes 0-8 evaluate the 9 LDSP candidates; lanes 9-13 speculatively
// evaluate the 5 SDSP candidates at the SAME center (valid when the loop exits
// with pt==4). SAD accumulation replicates XLA GPU's row-reduction association:
//   pacc[t] = |d|[t] + |d|[t+32], then tree offsets 16,8,4,2,1 (bit-exact argmin).
// Window stored NEGATED in two parity copies so each pairwise diff is one packed
// add on an aligned LDS.64 operand; reduction stays packed until the last level.
// zbase: z-chunk offset (motion is split into 3 launches so ncu's "-s 5" lands
// on a motion chunk instead of always sampling out_kernel).
__global__ __launch_bounds__(128) void motion_kernel(const float* __restrict__ x,
                                                     int zbase) {
    __shared__ __align__(16) float swin [24 * SW];  // -ref window, rows [i-8,i+16), cols [j0-8,j0+72)
    __shared__ __align__(16) float swin1[24 * SW];  // same, shifted: swin1[r][c] = -win[r][c+1]
    __shared__ __align__(16) float sblk [8 * 64];   // current-frame blocks for this tile

    const int jt  = blockIdx.x;              // col tile 0..7
    const int bi  = blockIdx.y;              // block row 0..63
    const int bp_ = blockIdx.z + zbase;      // b*NPAIR + p, 0..55
    const int b   = bp_ / NPAIR;
    const int p   = bp_ % NPAIR;

    const float* imgI = x + (size_t)(b * 16 + p) * HH * WW;       // reference (t-1)
    const float* imgP = imgI + (size_t)HH * WW;                   // current  (t)

    const int i  = bi * MBS;
    const int j0 = jt * 64;
    const int tid = threadIdx.x;

    // Cooperative loads (clamped; out-of-range rows/cols only back invalid candidates)
    for (int t = tid; t < 24 * 80; t += 128) {
        int r = t / 80, c = t - (t / 80) * 80;
        int gr = i - 8 + r;  gr = gr < 0 ? 0 : (gr > HH - 1 ? HH - 1 : gr);
        int gc = j0 - 8 + c; gc = gc < 0 ? 0 : (gc > WW - 1 ? WW - 1 : gc);
        float v = -imgI[gr * WW + gc];               // NEGATED for packed-add subtraction
        swin[r * SW + c] = v;
        if (c > 0) swin1[r * SW + (c - 1)] = v;
    }
    for (int t = tid; t < 8 * 64; t += 128) {
        int r = t >> 6, c = t & 63;
        sblk[t] = imgP[(i + r) * WW + (j0 + c)];
    }
    __syncthreads();

    const int g  = tid >> 4;       // group (macroblock) 0..7
    const int lg = tid & 15;       // lane in group
    const int base16 = tid & 16;
    const unsigned gmask = 0xFFFFu << base16;
    const int j = j0 + g * 8;
    const float* bb = sblk + g * 8;

    // SAD mean, XLA association, packed throughout.
    auto evalc = [&](int cy, int cx) -> float {
        const int row = cy - i + 8;
        const int o   = cx - j0 + 8;
        const float* wp = (o & 1) ? (swin1 + row * SW + (o - 1))
                                  : (swin  + row * SW + o);
        ull pk[16];                 // pk[tp] = (pacc[2tp], pacc[2tp+1])
#pragma unroll
        for (int tp = 0; tp < 16; tp++) {
            int t  = tp * 2;
            int r0 = t >> 3, c0_ = t & 7;   // elements (t, t+1): same row
            int r1 = r0 + 4;                // elements (t+32, t+33)
            ull bu0 = *(const ull*)(bb + r0 * 64 + c0_);
            ull bu1 = *(const ull*)(bb + r1 * 64 + c0_);
            ull wu0 = *(const ull*)(wp + r0 * SW + c0_);
            ull wu1 = *(const ull*)(wp + r1 * SW + c0_);
            ull d0 = absp(addp(bu0, wu0));  // |b - w| packed, elements t, t+1
            ull d1 = absp(addp(bu1, wu1));  // elements t+32, t+33
            pk[tp] = addp(d0, d1);          // pacc[t], pacc[t+1]
        }
        // Scalar tree offsets 16,8,4,2 == packed offsets 8,4,2,1 (elementwise).
#pragma unroll
        for (int off = 8; off >= 1; off >>= 1)
#pragma unroll
            for (int u = 0; u < 8; u++)
                if (u < off) pk[u] = addp(pk[u], pk[u + off]);
        // Final scalar level (off=1): pacc[0] + pacc[1].
        float lo, hi;
        asm("mov.b64 {%0, %1}, %2;" : "=f"(lo), "=f"(hi) : "l"(pk[0]));
        return (lo + hi) * 0.015625f;
    };

    auto costat = [&](int cy, int cx) -> float {
        bool valid = (cy >= 0) && (cy + MBS <= HH) && (cx >= 0) && (cx + MBS <= WW)
                   && (cy - i <= PR) && (i - cy <= PR) && (cx - j <= PR) && (j - cx <= PR);
        float cst = LARGEC;
        if (valid) cst = evalc(cy, cx);
        return cst;
    };

    // Lane role: 0-8 LDSP, 9-13 SDSP(lg-9), 14-15 dup SDSP center (unused).
    const bool isldsp = (lg < 9);
    const int  sdi    = (lg >= 9 && lg < 14) ? (lg - 9) : 2;
    const int  mdy    = isldsp ? c_ldsp_dy[lg] : c_sdsp_dy[sdi];
    const int  mdx    = isldsp ? c_ldsp_dx[lg] : c_sdsp_dx[sdi];

    int y = i, xx = j;
    float my_sdsp = FLT_MAX;
    bool have_sdsp = false;

    for (int k = 0; k < MAX_STEPS; k++) {
        float cost = costat(y + mdy, xx + mdx);
        if (lg >= 9) my_sdsp = cost;

        if (k == 0) {
            // Reference's standalone c0 check == this iteration's lane 4 cost.
            float ctr = __shfl_sync(gmask, cost, 4, 16);
            if (ctr == 0.0f) { have_sdsp = true; break; }
        }

        // LDSP argmin via redux+ballot+ffs (3 dependent steps vs 4 shfl rounds).
        int idx = argmin16(isldsp ? cost : FLT_MAX, gmask, base16);
        if (idx == 4) { have_sdsp = true; break; }   // center: speculative SDSP valid
        y  += c_ldsp_dy[idx];
        xx += c_ldsp_dx[idx];
    }

    // SDSP refinement: use speculative costs, or (rare: MAX_STEPS exit) recompute.
    {
        int si;
        if (have_sdsp) {
            float v = (lg >= 9 && lg < 14) ? my_sdsp : FLT_MAX;
            si = argmin16(v, gmask, base16) - 9;      // lane 9..13 -> idx 0..4
        } else {
            float v = (lg < 5) ? costat(y + c_sdsp_dy[lg], xx + c_sdsp_dx[lg]) : FLT_MAX;
            si = argmin16(v, gmask, base16);          // lane 0..4 -> idx 0..4
        }
        y  += c_sdsp_dy[si];
        xx += c_sdsp_dx[si];
    }

    if (lg == 0) {
        g_motion[(bp_ * NBR + bi) * NBC + (jt * 8 + g)] = make_int2(y - i, xx - j);
    }
}

// Output: first half = target (crop of frame f+2), second half = pred
// (motion-compensated warp of frame f+1 through g_motion, cropped).
// 4 rows per thread -> 8+ independent loads in flight (L2-latency bound).
__global__ void out_kernel(const float* __restrict__ x, float* __restrict__ out) {
    int c = blockIdx.x * blockDim.x + threadIdx.x;
    if (c >= OUTD) return;
    int rb = blockIdx.y * 4;          // rows rb .. rb+3 (guarded; 478 = 4*119+2)
    int z  = blockIdx.z;              // b*NPAIR + f
    int b = z / NPAIR;
    int f = z - b * NPAIR;

    const float* base = x + (size_t)b * 16 * HH * WW;
    const float* tgt  = base + (size_t)(f + 2) * HH * WW;
    const float* ref  = base + (size_t)(f + 1) * HH * WW;
    const size_t TOT = (size_t)NBATCH * NPAIR * OUTD * OUTD;
    const int2* mrow = &g_motion[(b * NPAIR + f) * NBR * NBC];

    int C = CROPX + c;
    int cb = C >> 3;

    float t_[4], p_[4];
    int nr = (OUTD - rb) < 4 ? (OUTD - rb) : 4;

#pragma unroll
    for (int u = 0; u < 4; u++) {
        if (u < nr) {
            int R = CROPX + rb + u;
            t_[u] = tgt[(size_t)R * WW + C];
            int2 m = mrow[(R >> 3) * NBC + cb];
            p_[u] = ref[(size_t)(R + m.x) * WW + (C + m.y)];
        }
    }

    size_t o = ((size_t)z * OUTD + rb) * OUTD + c;
#pragma unroll
    for (int u = 0; u < 4; u++) {
        if (u < nr) {
            out[o + (size_t)u * OUTD] = t_[u];
            out[TOT + o + (size_t)u * OUTD] = p_[u];
        }
    }
}

extern "C" void kernel_launch(void* const* d_in, const int* in_sizes, int n_in,
                              void* d_out, int out_size) {
    const float* x = (const float*)d_in[0];
    float* out = (float*)d_out;

    // Motion split into 3 z-chunks: 4-launch pattern puts launch index 5
    // (ncu -s 5 -c 1) on a motion chunk instead of out_kernel.
    dim3 gm1(8, 64, 19), gm2(8, 64, 19), gm3(8, 64, 18);
    motion_kernel<<<gm1, 128>>>(x, 0);
    motion_kernel<<<gm2, 128>>>(x, 19);
    motion_kernel<<<gm3, 128>>>(x, 38);

    dim3 go((OUTD + 255) / 256, (OUTD + 3) / 4, NBATCH * NPAIR);
    out_kernel<<<go, 256>>>(x, out);
}

// round 13
// speedup vs baseline: 1.0377x; 1.0377x over previous
#include <cuda_runtime.h>
#include <float.h>

// Problem constants
#define HH 512
#define WW 512
#define MBS 8
#define PR 8
#define NBR 64
#define NBC 64
#define NPAIR 14
#define NBATCH 4
#define CROPX 17
#define OUTD 478
#define LARGEC 65537.0f
#define MAX_STEPS 16
#define SW 84          // padded smem window stride (cols)

typedef unsigned long long ull;

__device__ int2 g_motion[NBATCH * NPAIR * NBR * NBC];

// LDSP points as (dx, dy) matching reference ordering; cost uses (y+dy, x+dx).
__constant__ int c_ldsp_dx[9] = { 0, -1, 1, -2, 0, 2, -1, 1, 0 };
__constant__ int c_ldsp_dy[9] = { -2, -1, -1, 0, 0, 0, 1, 1, 2 };
__constant__ int c_sdsp_dx[5] = { 0, -1, 0, 1, 0 };
__constant__ int c_sdsp_dy[5] = { -1, 0, 0, 0, 1 };
// Combined delta table for the 14 cached lanes: 0-8 LDSP, 9-13 SDSP.
__constant__ int c_all_dx[14] = { 0, -1, 1, -2, 0, 2, -1, 1, 0,   0, -1, 0, 1, 0 };
__constant__ int c_all_dy[14] = { -2, -1, -1, 0, 0, 0, 1, 1, 2,  -1,  0, 0, 0, 1 };

// Packed fp32x2 add (sm_103a): rounding identical to scalar FADD per lane.
__device__ __forceinline__ ull addp(ull a, ull b) {
    ull d;
    asm("add.rn.f32x2 %0, %1, %2;" : "=l"(d) : "l"(a), "l"(b));
    return d;
}
// Packed abs: clear both sign bits (bit-exact |x|); ALU pipe.
__device__ __forceinline__ ull absp(ull a) {
    ull d;
    asm("and.b64 %0, %1, 0x7FFFFFFF7FFFFFFF;" : "=l"(d) : "l"(a));
    return d;
}

// First-index argmin over a 16-lane group. Costs are >= 0 so u32 order on the
// bit patterns == float order; idle lanes pass FLT_MAX. Lowest matching lane
// == jnp.argmin first-index (lane-in-group is candidate index).
__device__ __forceinline__ int argmin16(float v, unsigned gmask, int base) {
    unsigned bits = __float_as_uint(v);
    unsigned mn;
    asm("redux.sync.min.u32 %0, %1, %2;" : "=r"(mn) : "r"(bits), "r"(gmask));
    unsigned bal = __ballot_sync(gmask, bits == mn);
    return __ffs(bal >> base) - 1;
}

// One CTA: 8 macroblocks. 128 threads = 8 groups of 16 lanes.
// Lanes 0-8: LDSP candidates; lanes 9-13: speculative SDSP at the center
// (valid when the loop exits with pt==4). SAD accumulation replicates XLA GPU's
// row-reduction association (pacc[t]=|d|[t]+|d|[t+32], tree 16/8/4/2/1) —
// bit-exact argmin vs the reference.
// CROSS-ROUND REUSE: after a move d_m, a lane whose new delta T satisfies
// d_m + T ∈ {14 cached deltas} takes last round's cost from that lane via shfl
// (deterministic SAD -> bit-identical) instead of re-evaluating. ~half of all
// SAD evals eliminated.
__global__ __launch_bounds__(128) void motion_kernel(const float* __restrict__ x) {
    __shared__ __align__(16) float swin [24 * SW];  // -ref window
    __shared__ __align__(16) float swin1[24 * SW];  // shifted copy: swin1[r][c] = -win[r][c+1]
    __shared__ __align__(16) float sblk [8 * 64];

    const int jt  = blockIdx.x;
    const int bi  = blockIdx.y;
    const int bp_ = blockIdx.z;              // b*NPAIR + p
    const int b   = bp_ / NPAIR;
    const int p   = bp_ % NPAIR;

    const float* imgI = x + (size_t)(b * 16 + p) * HH * WW;
    const float* imgP = imgI + (size_t)HH * WW;

    const int i  = bi * MBS;
    const int j0 = jt * 64;
    const int tid = threadIdx.x;

    for (int t = tid; t < 24 * 80; t += 128) {
        int r = t / 80, c = t - (t / 80) * 80;
        int gr = i - 8 + r;  gr = gr < 0 ? 0 : (gr > HH - 1 ? HH - 1 : gr);
        int gc = j0 - 8 + c; gc = gc < 0 ? 0 : (gc > WW - 1 ? WW - 1 : gc);
        float v = -imgI[gr * WW + gc];               // negated for packed-add subtraction
        swin[r * SW + c] = v;
        if (c > 0) swin1[r * SW + (c - 1)] = v;
    }
    for (int t = tid; t < 8 * 64; t += 128) {
        int r = t >> 6, c = t & 63;
        sblk[t] = imgP[(i + r) * WW + (j0 + c)];
    }
    __syncthreads();

    const int g  = tid >> 4;
    const int lg = tid & 15;
    const int base16 = tid & 16;
    const unsigned gmask = 0xFFFFu << base16;
    const int j = j0 + g * 8;
    const float* bb = sblk + g * 8;

    auto evalc = [&](int cy, int cx) -> float {
        const int row = cy - i + 8;
        const int o   = cx - j0 + 8;
        const float* wp = (o & 1) ? (swin1 + row * SW + (o - 1))
                                  : (swin  + row * SW + o);
        ull pk[16];
#pragma unroll
        for (int tp = 0; tp < 16; tp++) {
            int t  = tp * 2;
            int r0 = t >> 3, c0_ = t & 7;
            int r1 = r0 + 4;
            ull bu0 = *(const ull*)(bb + r0 * 64 + c0_);
            ull bu1 = *(const ull*)(bb + r1 * 64 + c0_);
            ull wu0 = *(const ull*)(wp + r0 * SW + c0_);
            ull wu1 = *(const ull*)(wp + r1 * SW + c0_);
            ull d0 = absp(addp(bu0, wu0));
            ull d1 = absp(addp(bu1, wu1));
            pk[tp] = addp(d0, d1);
        }
#pragma unroll
        for (int off = 8; off >= 1; off >>= 1)
#pragma unroll
            for (int u = 0; u < 8; u++)
                if (u < off) pk[u] = addp(pk[u], pk[u + off]);
        float lo, hi;
        asm("mov.b64 {%0, %1}, %2;" : "=f"(lo), "=f"(hi) : "l"(pk[0]));
        return (lo + hi) * 0.015625f;
    };

    auto costat = [&](int cy, int cx) -> float {
        bool valid = (cy >= 0) && (cy + MBS <= HH) && (cx >= 0) && (cx + MBS <= WW)
                   && (cy - i <= PR) && (i - cy <= PR) && (cx - j <= PR) && (j - cx <= PR);
        float cst = LARGEC;
        if (valid) cst = evalc(cy, cx);
        return cst;
    };

    // Lane role: 0-8 LDSP, 9-13 SDSP(lg-9), 14-15 dup SDSP center.
    const bool isldsp = (lg < 9);
    const int  sdi    = (lg >= 9 && lg < 14) ? (lg - 9) : 2;
    const int  mdy    = isldsp ? c_ldsp_dy[lg] : c_sdsp_dy[sdi];
    const int  mdx    = isldsp ? c_ldsp_dx[lg] : c_sdsp_dx[sdi];

    int y = i, xx = j;
    bool have_sdsp = false;
    float cost = costat(y + mdy, xx + mdx);   // round 0: full eval, all 16 lanes

    for (int k = 0; k < MAX_STEPS; k++) {
        if (k == 0) {
            // Reference's standalone c0 check == lane 4's cost this round.
            float ctr = __shfl_sync(gmask, cost, 4, 16);
            if (ctr == 0.0f) { have_sdsp = true; break; }
        }

        int idx = argmin16(isldsp ? cost : FLT_MAX, gmask, base16);
        if (idx == 4) { have_sdsp = true; break; }   // center: lanes 9-13 hold SDSP

        // Cross-round reuse: my new absolute delta rel. old center.
        int tdx = c_ldsp_dx[idx] + mdx;
        int tdy = c_ldsp_dy[idx] + mdy;
        int src = 16;
#pragma unroll
        for (int s = 0; s < 14; s++)
            if (c_all_dx[s] == tdx && c_all_dy[s] == tdy) src = s;
        float cached = __shfl_sync(gmask, cost, src & 15, 16);

        y  += c_ldsp_dy[idx];
        xx += c_ldsp_dx[idx];

        if (src < 14) cost = cached;                  // bit-identical reuse
        else          cost = costat(y + mdy, xx + mdx);
    }

    // SDSP refinement: speculative costs (lanes 9-13), or fallback recompute.
    {
        int si;
        if (have_sdsp) {
            float v = (lg >= 9 && lg < 14) ? cost : FLT_MAX;
            si = argmin16(v, gmask, base16) - 9;      // lane 9..13 -> idx 0..4
        } else {
            float v = (lg < 5) ? costat(y + c_sdsp_dy[lg], xx + c_sdsp_dx[lg]) : FLT_MAX;
            si = argmin16(v, gmask, base16);
        }
        y  += c_sdsp_dy[si];
        xx += c_sdsp_dx[si];
    }

    if (lg == 0) {
        g_motion[(bp_ * NBR + bi) * NBC + (jt * 8 + g)] = make_int2(y - i, xx - j);
    }
}

// Output: first half = target (crop of frame f+2), second half = pred
// (motion-compensated warp of frame f+1 through g_motion, cropped).
// 4 rows per thread -> 8+ independent loads in flight (L2-latency bound).
__global__ void out_kernel(const float* __restrict__ x, float* __restrict__ out) {
    int c = blockIdx.x * blockDim.x + threadIdx.x;
    if (c >= OUTD) return;
    int rb = blockIdx.y * 4;
    int z  = blockIdx.z;
    int b = z / NPAIR;
    int f = z - b * NPAIR;

    const float* base = x + (size_t)b * 16 * HH * WW;
    const float* tgt  = base + (size_t)(f + 2) * HH * WW;
    const float* ref  = base + (size_t)(f + 1) * HH * WW;
    const size_t TOT = (size_t)NBATCH * NPAIR * OUTD * OUTD;
    const int2* mrow = &g_motion[(b * NPAIR + f) * NBR * NBC];

    int C = CROPX + c;
    int cb = C >> 3;

    float t_[4], p_[4];
    int nr = (OUTD - rb) < 4 ? (OUTD - rb) : 4;

#pragma unroll
    for (int u = 0; u < 4; u++) {
        if (u < nr) {
            int R = CROPX + rb + u;
            t_[u] = tgt[(size_t)R * WW + C];
            int2 m = mrow[(R >> 3) * NBC + cb];
            p_[u] = ref[(size_t)(R + m.x) * WW + (C + m.y)];
        }
    }

    size_t o = ((size_t)z * OUTD + rb) * OUTD + c;
#pragma unroll
    for (int u = 0; u < 4; u++) {
        if (u < nr) {
            out[o + (size_t)u * OUTD] = t_[u];
            out[TOT + o + (size_t)u * OUTD] = p_[u];
        }
    }
}

extern "C" void kernel_launch(void* const* d_in, const int* in_sizes, int n_in,
                              void* d_out, int out_size) {
    const float* x = (const float*)d_in[0];
    float* out = (float*)d_out;

    dim3 gm(8, 64, NBATCH * NPAIR);
    motion_kernel<<<gm, 128>>>(x);

    dim3 go((OUTD + 255) / 256, (OUTD + 3) / 4, NBATCH * NPAIR);
    out_kernel<<<go, 256>>>(x, out);
}